// round 13
// baseline (speedup 1.0000x reference)
#include <cuda_runtime.h>

#define B_ 32
#define L_ 4096
#define H_ 1024

#define GSPLIT 64                 // g-chunks for split-K projection
#define GCH    (H_ / GSPLIT)      // 16 g per chunk
#define BSPLIT 4                  // b-quarters
#define BCH    (B_ / BSPLIT)      // 8 b per block

#define BG     8                  // b per energies block
#define LG     8                  // l per energies block

// Scratch
__device__ float g_vp[GSPLIT * B_ * H_];   // 8 MB split-K partials
__device__ float g_v[B_ * H_];             // projected hidden
__device__ int   g_cnt[B_];                // softmax arrival counters
// (counters zero-init, self-resetting -> graph-replay-safe)

// ---------------------------------------------------------------------------
// Kernel A1: split-K partial projection (R10 config: best measured).
// ---------------------------------------------------------------------------
__global__ void proj_partial(const float* __restrict__ hid,
                             const float* __restrict__ W) {
    const int h  = blockIdx.x * 128 + threadIdx.x;
    const int gc = blockIdx.y;
    const int bq = blockIdx.z;

    __shared__ float sh[BCH][GCH];
    for (int i = threadIdx.x; i < BCH * GCH; i += 128) {
        const int b = i / GCH, g = i % GCH;
        sh[b][g] = hid[(bq * BCH + b) * H_ + gc * GCH + g];
    }
    __syncthreads();

    float acc[BCH];
#pragma unroll
    for (int b = 0; b < BCH; ++b) acc[b] = 0.f;

    const float* __restrict__ Wp = W + (size_t)(gc * GCH) * H_ + h;
#pragma unroll
    for (int g = 0; g < GCH; ++g) {
        const float w = Wp[(size_t)g * H_];
#pragma unroll
        for (int b = 0; b < BCH; ++b)
            acc[b] = fmaf(sh[b][g], w, acc[b]);
    }

    float* __restrict__ outp =
        g_vp + ((size_t)gc * B_ + bq * BCH) * H_ + h;
#pragma unroll
    for (int b = 0; b < BCH; ++b) outp[(size_t)b * H_] = acc[b];
}

// ---------------------------------------------------------------------------
// Kernel A2: reduce partials (L2-hot, 8 MB).
// ---------------------------------------------------------------------------
__global__ void proj_reduce() {
    const int i = blockIdx.x * 128 + threadIdx.x;
    float s = 0.f;
#pragma unroll
    for (int c = 0; c < GSPLIT; ++c)
        s += g_vp[(size_t)c * (B_ * H_) + i];
    g_v[i] = s;
}

// ---------------------------------------------------------------------------
// Kernel B: energies + fused softmax epilogue, contiguity-remapped.
// Block = 8 b x 8 l (grid 512 x 4 = 2048 blocks, 512 threads).
// Warp w: b_local = w & 7, handles 4 consecutive l (lg = w >> 3).
// For each l the block's 8 b-rows are CONTIGUOUS 32 KB in enc (vs 4 KB
// stretches before). v for the 8 b's lives in smem (32 KB).
// Per-b arrival counters: last block for a b softmaxes that row in place.
// ---------------------------------------------------------------------------
__global__ void energies_softmax(const float* __restrict__ enc,
                                 float* __restrict__ out) {
    const int bg   = blockIdx.y;          // b-group (8 b)
    const int tid  = threadIdx.x;
    const int warp = tid >> 5;
    const int lane = tid & 31;
    const int b_local = warp & 7;
    const int lg      = warp >> 3;        // 0 or 1

    __shared__ float4 sv[BG][H_ / 4];     // 32 KB
    __shared__ float  red[16];
    __shared__ int    s_claim[BG];

    {
        const float4* __restrict__ v4 =
            (const float4*)(g_v + (size_t)bg * BG * H_);
        for (int i = tid; i < BG * (H_ / 4); i += 512)
            sv[i / (H_ / 4)][i % (H_ / 4)] = v4[i];
    }
    __syncthreads();

    const int b  = bg * BG + b_local;
    const int l0 = blockIdx.x * LG + lg * 4;         // 4 rows per warp
    const float4* __restrict__ base =
        (const float4*)(enc + ((size_t)l0 * B_ + b) * (size_t)H_);
    const size_t row4 = (size_t)B_ * H_ / 4;

    float s[4] = {0.f, 0.f, 0.f, 0.f};
#pragma unroll
    for (int i = 0; i < 8; ++i) {
        const float4 vv = sv[b_local][i * 32 + lane];
#pragma unroll
        for (int j = 0; j < 4; ++j) {
            float4 e = __ldcs(&base[(size_t)j * row4 + i * 32 + lane]);
            s[j] = fmaf(vv.x, e.x, s[j]);
            s[j] = fmaf(vv.y, e.y, s[j]);
            s[j] = fmaf(vv.z, e.z, s[j]);
            s[j] = fmaf(vv.w, e.w, s[j]);
        }
    }

#pragma unroll
    for (int j = 0; j < 4; ++j) {
        float t = s[j];
#pragma unroll
        for (int o = 16; o; o >>= 1)
            t += __shfl_down_sync(0xffffffffu, t, o);
        if (lane == 0) out[b * L_ + l0 + j] = t;
    }

    // ---- arrival on the 8 per-b counters of this b-group ----
    __threadfence();
    __syncthreads();
    if (tid < BG) {
        const int old = atomicAdd(&g_cnt[bg * BG + tid], 1);
        s_claim[tid] = (old == gridDim.x - 1);
    }
    __syncthreads();

    // ---- softmax any rows this block was last to finish ----
    for (int bb = 0; bb < BG; ++bb) {
        if (!s_claim[bb]) continue;
        __syncthreads();                     // protect red[] reuse
        const int brow = bg * BG + bb;
        float4* __restrict__ o4 = (float4*)(out + brow * L_);
        float4 x0 = o4[tid];
        float4 x1 = o4[tid + 512];

        float m = fmaxf(fmaxf(fmaxf(x0.x, x0.y), fmaxf(x0.z, x0.w)),
                        fmaxf(fmaxf(x1.x, x1.y), fmaxf(x1.z, x1.w)));
#pragma unroll
        for (int o = 16; o; o >>= 1)
            m = fmaxf(m, __shfl_xor_sync(0xffffffffu, m, o));
        if (lane == 0) red[warp] = m;
        __syncthreads();
        if (tid < 32) {
            float t = (lane < 16) ? red[lane] : -1e30f;
#pragma unroll
            for (int o = 8; o; o >>= 1)
                t = fmaxf(t, __shfl_xor_sync(0xffffffffu, t, o));
            red[lane & 15] = t;
        }
        __syncthreads();
        m = red[0];

        x0.x = __expf(x0.x - m); x0.y = __expf(x0.y - m);
        x0.z = __expf(x0.z - m); x0.w = __expf(x0.w - m);
        x1.x = __expf(x1.x - m); x1.y = __expf(x1.y - m);
        x1.z = __expf(x1.z - m); x1.w = __expf(x1.w - m);
        float sum = ((x0.x + x0.y) + (x0.z + x0.w)) +
                    ((x1.x + x1.y) + (x1.z + x1.w));
#pragma unroll
        for (int o = 16; o; o >>= 1)
            sum += __shfl_xor_sync(0xffffffffu, sum, o);
        __syncthreads();
        if (lane == 0) red[warp] = sum;
        __syncthreads();
        if (tid < 32) {
            float t = (lane < 16) ? red[lane] : 0.f;
#pragma unroll
            for (int o = 8; o; o >>= 1)
                t += __shfl_xor_sync(0xffffffffu, t, o);
            red[lane & 15] = t;
        }
        __syncthreads();
        const float inv = 1.f / red[0];

        x0.x *= inv; x0.y *= inv; x0.z *= inv; x0.w *= inv;
        x1.x *= inv; x1.y *= inv; x1.z *= inv; x1.w *= inv;
        o4[tid]       = x0;
        o4[tid + 512] = x1;

        if (tid == 0) g_cnt[brow] = 0;   // self-reset for next replay
    }
}

// ---------------------------------------------------------------------------
extern "C" void kernel_launch(void* const* d_in, const int* in_sizes, int n_in,
                              void* d_out, int out_size) {
    const float* hid = (const float*)d_in[0];   // [1,B,H]
    const float* enc = (const float*)d_in[1];   // [L,B,H]
    const float* W   = (const float*)d_in[2];   // [H,H]
    // d_in[3] = bias: irrelevant (softmax shift invariance)
    float* out = (float*)d_out;                 // [B,1,L]

    proj_partial    <<<dim3(H_ / 128, GSPLIT, BSPLIT), 128>>>(hid, W);
    proj_reduce     <<<B_ * H_ / 128, 128>>>();
    energies_softmax<<<dim3(L_ / LG, B_ / BG), 512>>>(enc, out);
}

// round 14
// speedup vs baseline: 1.0380x; 1.0380x over previous
#include <cuda_runtime.h>

#define B_ 32
#define L_ 4096
#define H_ 1024

#define GSPLIT 64                 // g-chunks for split-K projection
#define GCH    (H_ / GSPLIT)      // 16 g per chunk
#define BSPLIT 4                  // b-quarters
#define BCH    (B_ / BSPLIT)      // 8 b per block

// Scratch
__device__ float g_vp[GSPLIT * B_ * H_];   // 8 MB split-K partials
__device__ float g_v[B_ * H_];             // projected hidden
__device__ int   g_cnt[B_];                // arrival counters (zero-init,
                                           // self-resetting -> replay-safe)

// ---------------------------------------------------------------------------
// Kernel A1: split-K partial projection (R10 config: best measured 7.9us).
//   vp[gc, b, h] = sum_{g in chunk gc} hid[b,g] * W[g,h]
// Grid (8, 64, 4) = 2048 blocks x 128 thr, 8 accumulators/thread (40 regs).
// ---------------------------------------------------------------------------
__global__ void __launch_bounds__(128, 16)
proj_partial(const float* __restrict__ hid,
             const float* __restrict__ W) {
    const int h  = blockIdx.x * 128 + threadIdx.x;
    const int gc = blockIdx.y;
    const int bq = blockIdx.z;                 // b-quarter

    __shared__ float sh[BCH][GCH];             // 512 B
    for (int i = threadIdx.x; i < BCH * GCH; i += 128) {
        const int b = i / GCH, g = i % GCH;
        sh[b][g] = hid[(bq * BCH + b) * H_ + gc * GCH + g];
    }
    __syncthreads();

    float acc[BCH];
#pragma unroll
    for (int b = 0; b < BCH; ++b) acc[b] = 0.f;

    const float* __restrict__ Wp = W + (size_t)(gc * GCH) * H_ + h;
#pragma unroll
    for (int g = 0; g < GCH; ++g) {
        const float w = Wp[(size_t)g * H_];    // coalesced
#pragma unroll
        for (int b = 0; b < BCH; ++b)
            acc[b] = fmaf(sh[b][g], w, acc[b]);
    }

    float* __restrict__ outp =
        g_vp + ((size_t)gc * B_ + bq * BCH) * H_ + h;
#pragma unroll
    for (int b = 0; b < BCH; ++b) outp[(size_t)b * H_] = acc[b];
}

// ---------------------------------------------------------------------------
// Kernel A2: reduce partials (L2-hot, 8 MB), float4-vectorized.
// 8192 threads x 64 float4 loads: 4x bytes per load slot vs scalar version.
// ---------------------------------------------------------------------------
__global__ void proj_reduce() {
    const int i = blockIdx.x * 128 + threadIdx.x;   // 0 .. B*H/4-1
    const float4* __restrict__ vp4 = (const float4*)g_vp;
    float4 s = make_float4(0.f, 0.f, 0.f, 0.f);
#pragma unroll
    for (int c = 0; c < GSPLIT; ++c) {
        float4 p = vp4[(size_t)c * (B_ * H_ / 4) + i];
        s.x += p.x; s.y += p.y; s.z += p.z; s.w += p.w;
    }
    ((float4*)g_v)[i] = s;
}

// ---------------------------------------------------------------------------
// Kernel B: energies + fused softmax epilogue (R10 exact: 86.5us measured,
// DRAM 78.9% -- at this pattern's ceiling).
// ---------------------------------------------------------------------------
__global__ void energies_softmax(const float* __restrict__ enc,
                                 float* __restrict__ out) {
    const int b    = blockIdx.y;
    const int tid  = threadIdx.x;
    const int warp = tid >> 5;
    const int lane = tid & 31;

    __shared__ float4 sv[H_ / 4];   // 4 KB: v[b]
    __shared__ float  red[16];
    __shared__ int    s_last;

    {
        const float4* __restrict__ v4 = (const float4*)(g_v + b * H_);
        for (int i = tid; i < H_ / 4; i += 512) sv[i] = v4[i];
    }
    __syncthreads();

    const int l0 = (blockIdx.x * 16 + warp) * 4;     // 4 rows per warp
    const float4* __restrict__ base =
        (const float4*)(enc + ((size_t)l0 * B_ + b) * (size_t)H_);
    const size_t row4 = (size_t)B_ * H_ / 4;

    float s[4] = {0.f, 0.f, 0.f, 0.f};
#pragma unroll
    for (int i = 0; i < 8; ++i) {
        const float4 vv = sv[i * 32 + lane];
#pragma unroll
        for (int j = 0; j < 4; ++j) {
            float4 e = __ldcs(&base[(size_t)j * row4 + i * 32 + lane]);
            s[j] = fmaf(vv.x, e.x, s[j]);
            s[j] = fmaf(vv.y, e.y, s[j]);
            s[j] = fmaf(vv.z, e.z, s[j]);
            s[j] = fmaf(vv.w, e.w, s[j]);
        }
    }

#pragma unroll
    for (int j = 0; j < 4; ++j) {
        float t = s[j];
#pragma unroll
        for (int o = 16; o; o >>= 1)
            t += __shfl_down_sync(0xffffffffu, t, o);
        if (lane == 0) out[b * L_ + l0 + j] = t;
    }

    // ---- arrival: is this the last block for row b? ----
    __threadfence();
    __syncthreads();
    if (tid == 0) {
        const int old = atomicAdd(&g_cnt[b], 1);
        s_last = (old == gridDim.x - 1);
    }
    __syncthreads();
    if (!s_last) return;

    // ---- softmax epilogue on L2-hot row (one block per b) ----
    float4* __restrict__ o4 = (float4*)(out + b * L_);   // 1024 float4
    float4 x0 = o4[tid];
    float4 x1 = o4[tid + 512];

    float m = fmaxf(fmaxf(fmaxf(x0.x, x0.y), fmaxf(x0.z, x0.w)),
                    fmaxf(fmaxf(x1.x, x1.y), fmaxf(x1.z, x1.w)));
#pragma unroll
    for (int o = 16; o; o >>= 1) m = fmaxf(m, __shfl_xor_sync(0xffffffffu, m, o));
    if (lane == 0) red[warp] = m;
    __syncthreads();
    if (tid < 32) {
        float t = (lane < 16) ? red[lane] : -1e30f;
#pragma unroll
        for (int o = 8; o; o >>= 1) t = fmaxf(t, __shfl_xor_sync(0xffffffffu, t, o));
        red[lane & 15] = t;
    }
    __syncthreads();
    m = red[0];

    x0.x = __expf(x0.x - m); x0.y = __expf(x0.y - m);
    x0.z = __expf(x0.z - m); x0.w = __expf(x0.w - m);
    x1.x = __expf(x1.x - m); x1.y = __expf(x1.y - m);
    x1.z = __expf(x1.z - m); x1.w = __expf(x1.w - m);
    float sum = ((x0.x + x0.y) + (x0.z + x0.w)) +
                ((x1.x + x1.y) + (x1.z + x1.w));
#pragma unroll
    for (int o = 16; o; o >>= 1) sum += __shfl_xor_sync(0xffffffffu, sum, o);
    __syncthreads();
    if (lane == 0) red[warp] = sum;
    __syncthreads();
    if (tid < 32) {
        float t = (lane < 16) ? red[lane] : 0.f;
#pragma unroll
        for (int o = 8; o; o >>= 1) t += __shfl_xor_sync(0xffffffffu, t, o);
        red[lane & 15] = t;
    }
    __syncthreads();
    const float inv = 1.f / red[0];

    x0.x *= inv; x0.y *= inv; x0.z *= inv; x0.w *= inv;
    x1.x *= inv; x1.y *= inv; x1.z *= inv; x1.w *= inv;
    o4[tid]       = x0;
    o4[tid + 512] = x1;

    if (tid == 0) g_cnt[b] = 0;      // self-reset for next replay
}

// ---------------------------------------------------------------------------
extern "C" void kernel_launch(void* const* d_in, const int* in_sizes, int n_in,
                              void* d_out, int out_size) {
    const float* hid = (const float*)d_in[0];   // [1,B,H]
    const float* enc = (const float*)d_in[1];   // [L,B,H]
    const float* W   = (const float*)d_in[2];   // [H,H]
    // d_in[3] = bias: irrelevant (softmax shift invariance)
    float* out = (float*)d_out;                 // [B,1,L]

    proj_partial    <<<dim3(H_ / 128, GSPLIT, BSPLIT), 128>>>(hid, W);
    proj_reduce     <<<B_ * H_ / 4 / 128, 128>>>();
    energies_softmax<<<dim3(L_ / 64, B_), 512>>>(enc, out);
}

// round 15
// speedup vs baseline: 1.1132x; 1.0725x over previous
#include <cuda_runtime.h>

#define B_ 32
#define L_ 4096
#define H_ 1024

#define GSPLIT 64                 // g-chunks for split-K projection
#define GCH    (H_ / GSPLIT)      // 16 g per chunk
#define BSPLIT 4                  // b-quarters
#define BCH    (B_ / BSPLIT)      // 8 b per block

// Scratch
__device__ float g_vp[GSPLIT * B_ * H_];   // 8 MB split-K partials
__device__ float g_v[B_ * H_];             // projected hidden
__device__ int   g_cnt[B_];                // arrival counters (zero-init,
                                           // self-resetting -> replay-safe)

// ---------------------------------------------------------------------------
// Kernel A1: split-K partial projection — R10 EXACT config (measured 7.9us,
// regs=40, occ=55.6%). NO __launch_bounds__: capping regs to 32 cut the
// batched W loads and cost +3.2us (R14 measurement).
//   vp[gc, b, h] = sum_{g in chunk gc} hid[b,g] * W[g,h]
// ---------------------------------------------------------------------------
__global__ void proj_partial(const float* __restrict__ hid,
                             const float* __restrict__ W) {
    const int h  = blockIdx.x * 128 + threadIdx.x;
    const int gc = blockIdx.y;
    const int bq = blockIdx.z;                 // b-quarter

    __shared__ float sh[BCH][GCH];             // 512 B
    for (int i = threadIdx.x; i < BCH * GCH; i += 128) {
        const int b = i / GCH, g = i % GCH;
        sh[b][g] = hid[(bq * BCH + b) * H_ + gc * GCH + g];
    }
    __syncthreads();

    float acc[BCH];
#pragma unroll
    for (int b = 0; b < BCH; ++b) acc[b] = 0.f;

    const float* __restrict__ Wp = W + (size_t)(gc * GCH) * H_ + h;
#pragma unroll
    for (int g = 0; g < GCH; ++g) {
        const float w = Wp[(size_t)g * H_];    // coalesced
#pragma unroll
        for (int b = 0; b < BCH; ++b)
            acc[b] = fmaf(sh[b][g], w, acc[b]);
    }

    float* __restrict__ outp =
        g_vp + ((size_t)gc * B_ + bq * BCH) * H_ + h;
#pragma unroll
    for (int b = 0; b < BCH; ++b) outp[(size_t)b * H_] = acc[b];
}

// ---------------------------------------------------------------------------
// Kernel A2: reduce partials (L2-hot, 8 MB), float4-vectorized.
// 8192 threads x 64 float4 loads: 4x bytes per load slot vs scalar version.
// ---------------------------------------------------------------------------
__global__ void proj_reduce() {
    const int i = blockIdx.x * 128 + threadIdx.x;   // 0 .. B*H/4-1
    const float4* __restrict__ vp4 = (const float4*)g_vp;
    float4 s = make_float4(0.f, 0.f, 0.f, 0.f);
#pragma unroll
    for (int c = 0; c < GSPLIT; ++c) {
        float4 p = vp4[(size_t)c * (B_ * H_ / 4) + i];
        s.x += p.x; s.y += p.y; s.z += p.z; s.w += p.w;
    }
    ((float4*)g_v)[i] = s;
}

// ---------------------------------------------------------------------------
// Kernel B: energies + fused softmax epilogue (R10 exact: 86.5us measured,
// DRAM 78.9% — at this access pattern's ceiling).
// ---------------------------------------------------------------------------
__global__ void energies_softmax(const float* __restrict__ enc,
                                 float* __restrict__ out) {
    const int b    = blockIdx.y;
    const int tid  = threadIdx.x;
    const int warp = tid >> 5;
    const int lane = tid & 31;

    __shared__ float4 sv[H_ / 4];   // 4 KB: v[b]
    __shared__ float  red[16];
    __shared__ int    s_last;

    {
        const float4* __restrict__ v4 = (const float4*)(g_v + b * H_);
        for (int i = tid; i < H_ / 4; i += 512) sv[i] = v4[i];
    }
    __syncthreads();

    const int l0 = (blockIdx.x * 16 + warp) * 4;     // 4 rows per warp
    const float4* __restrict__ base =
        (const float4*)(enc + ((size_t)l0 * B_ + b) * (size_t)H_);
    const size_t row4 = (size_t)B_ * H_ / 4;

    float s[4] = {0.f, 0.f, 0.f, 0.f};
#pragma unroll
    for (int i = 0; i < 8; ++i) {
        const float4 vv = sv[i * 32 + lane];
#pragma unroll
        for (int j = 0; j < 4; ++j) {
            float4 e = __ldcs(&base[(size_t)j * row4 + i * 32 + lane]);
            s[j] = fmaf(vv.x, e.x, s[j]);
            s[j] = fmaf(vv.y, e.y, s[j]);
            s[j] = fmaf(vv.z, e.z, s[j]);
            s[j] = fmaf(vv.w, e.w, s[j]);
        }
    }

#pragma unroll
    for (int j = 0; j < 4; ++j) {
        float t = s[j];
#pragma unroll
        for (int o = 16; o; o >>= 1)
            t += __shfl_down_sync(0xffffffffu, t, o);
        if (lane == 0) out[b * L_ + l0 + j] = t;
    }

    // ---- arrival: is this the last block for row b? ----
    __threadfence();
    __syncthreads();
    if (tid == 0) {
        const int old = atomicAdd(&g_cnt[b], 1);
        s_last = (old == gridDim.x - 1);
    }
    __syncthreads();
    if (!s_last) return;

    // ---- softmax epilogue on L2-hot row (one block per b) ----
    float4* __restrict__ o4 = (float4*)(out + b * L_);   // 1024 float4
    float4 x0 = o4[tid];
    float4 x1 = o4[tid + 512];

    float m = fmaxf(fmaxf(fmaxf(x0.x, x0.y), fmaxf(x0.z, x0.w)),
                    fmaxf(fmaxf(x1.x, x1.y), fmaxf(x1.z, x1.w)));
#pragma unroll
    for (int o = 16; o; o >>= 1) m = fmaxf(m, __shfl_xor_sync(0xffffffffu, m, o));
    if (lane == 0) red[warp] = m;
    __syncthreads();
    if (tid < 32) {
        float t = (lane < 16) ? red[lane] : -1e30f;
#pragma unroll
        for (int o = 8; o; o >>= 1) t = fmaxf(t, __shfl_xor_sync(0xffffffffu, t, o));
        red[lane & 15] = t;
    }
    __syncthreads();
    m = red[0];

    x0.x = __expf(x0.x - m); x0.y = __expf(x0.y - m);
    x0.z = __expf(x0.z - m); x0.w = __expf(x0.w - m);
    x1.x = __expf(x1.x - m); x1.y = __expf(x1.y - m);
    x1.z = __expf(x1.z - m); x1.w = __expf(x1.w - m);
    float sum = ((x0.x + x0.y) + (x0.z + x0.w)) +
                ((x1.x + x1.y) + (x1.z + x1.w));
#pragma unroll
    for (int o = 16; o; o >>= 1) sum += __shfl_xor_sync(0xffffffffu, sum, o);
    __syncthreads();
    if (lane == 0) red[warp] = sum;
    __syncthreads();
    if (tid < 32) {
        float t = (lane < 16) ? red[lane] : 0.f;
#pragma unroll
        for (int o = 8; o; o >>= 1) t += __shfl_xor_sync(0xffffffffu, t, o);
        red[lane & 15] = t;
    }
    __syncthreads();
    const float inv = 1.f / red[0];

    x0.x *= inv; x0.y *= inv; x0.z *= inv; x0.w *= inv;
    x1.x *= inv; x1.y *= inv; x1.z *= inv; x1.w *= inv;
    o4[tid]       = x0;
    o4[tid + 512] = x1;

    if (tid == 0) g_cnt[b] = 0;      // self-reset for next replay
}

// ---------------------------------------------------------------------------
extern "C" void kernel_launch(void* const* d_in, const int* in_sizes, int n_in,
                              void* d_out, int out_size) {
    const float* hid = (const float*)d_in[0];   // [1,B,H]
    const float* enc = (const float*)d_in[1];   // [L,B,H]
    const float* W   = (const float*)d_in[2];   // [H,H]
    // d_in[3] = bias: irrelevant (softmax shift invariance)
    float* out = (float*)d_out;                 // [B,1,L]

    proj_partial    <<<dim3(H_ / 128, GSPLIT, BSPLIT), 128>>>(hid, W);
    proj_reduce     <<<B_ * H_ / 4 / 128, 128>>>();
    energies_softmax<<<dim3(L_ / 64, B_), 512>>>(enc, out);
}

// round 16
// speedup vs baseline: 1.1990x; 1.0770x over previous
#include <cuda_runtime.h>

#define B_ 32
#define L_ 4096
#define H_ 1024

#define GSPLIT 32                 // g-chunks for split-K projection
#define GCH    (H_ / GSPLIT)      // 32 g per chunk
#define BSPLIT 4                  // b-quarters
#define BCH    (B_ / BSPLIT)      // 8 b per block

// Scratch
__device__ float g_vp[GSPLIT * B_ * H_];   // 4 MB split-K partials
__device__ float g_v[B_ * H_];             // projected hidden
__device__ int   g_cnt[B_];                // arrival counters (zero-init,
                                           // self-resetting -> replay-safe)

// ---------------------------------------------------------------------------
// Kernel A1: split-K partial projection.
//   vp[gc, b, h] = sum_{g in chunk gc} hid[b,g] * W[g,h]
// Grid (8, 32, 4) = 1024 blocks x 128 thr, 8 accumulators/thread (~40 regs).
// vs R10 (GSPLIT=64): same W traffic + FMA count, half the partial stores.
// NO __launch_bounds__ (R14: capping regs to 32 cost +3.2us).
// ---------------------------------------------------------------------------
__global__ void proj_partial(const float* __restrict__ hid,
                             const float* __restrict__ W) {
    const int h  = blockIdx.x * 128 + threadIdx.x;
    const int gc = blockIdx.y;
    const int bq = blockIdx.z;                 // b-quarter

    __shared__ float sh[BCH][GCH];             // 1 KB
    for (int i = threadIdx.x; i < BCH * GCH; i += 128) {
        const int b = i / GCH, g = i % GCH;
        sh[b][g] = hid[(bq * BCH + b) * H_ + gc * GCH + g];
    }
    __syncthreads();

    float acc[BCH];
#pragma unroll
    for (int b = 0; b < BCH; ++b) acc[b] = 0.f;

    const float* __restrict__ Wp = W + (size_t)(gc * GCH) * H_ + h;
#pragma unroll
    for (int g = 0; g < GCH; ++g) {
        const float w = Wp[(size_t)g * H_];    // coalesced
#pragma unroll
        for (int b = 0; b < BCH; ++b)
            acc[b] = fmaf(sh[b][g], w, acc[b]);
    }

    float* __restrict__ outp =
        g_vp + ((size_t)gc * B_ + bq * BCH) * H_ + h;
#pragma unroll
    for (int b = 0; b < BCH; ++b) outp[(size_t)b * H_] = acc[b];
}

// ---------------------------------------------------------------------------
// Kernel A2: reduce partials (L2-hot, 4 MB) — R10 scalar shape:
// 256 blocks x 128 threads, 32 independent scalar loads per thread.
// (float4 version shrank the grid to 64 blocks and LOST 3us — R15 data.)
// ---------------------------------------------------------------------------
__global__ void proj_reduce() {
    const int i = blockIdx.x * 128 + threadIdx.x;   // 0 .. B*H-1
    float s = 0.f;
#pragma unroll
    for (int c = 0; c < GSPLIT; ++c)
        s += g_vp[(size_t)c * (B_ * H_) + i];
    g_v[i] = s;
}

// ---------------------------------------------------------------------------
// Kernel B: energies + fused softmax epilogue (R10 exact: 86.5us measured,
// DRAM 78.9% — at this access pattern's ceiling).
// ---------------------------------------------------------------------------
__global__ void energies_softmax(const float* __restrict__ enc,
                                 float* __restrict__ out) {
    const int b    = blockIdx.y;
    const int tid  = threadIdx.x;
    const int warp = tid >> 5;
    const int lane = tid & 31;

    __shared__ float4 sv[H_ / 4];   // 4 KB: v[b]
    __shared__ float  red[16];
    __shared__ int    s_last;

    {
        const float4* __restrict__ v4 = (const float4*)(g_v + b * H_);
        for (int i = tid; i < H_ / 4; i += 512) sv[i] = v4[i];
    }
    __syncthreads();

    const int l0 = (blockIdx.x * 16 + warp) * 4;     // 4 rows per warp
    const float4* __restrict__ base =
        (const float4*)(enc + ((size_t)l0 * B_ + b) * (size_t)H_);
    const size_t row4 = (size_t)B_ * H_ / 4;

    float s[4] = {0.f, 0.f, 0.f, 0.f};
#pragma unroll
    for (int i = 0; i < 8; ++i) {
        const float4 vv = sv[i * 32 + lane];
#pragma unroll
        for (int j = 0; j < 4; ++j) {
            float4 e = __ldcs(&base[(size_t)j * row4 + i * 32 + lane]);
            s[j] = fmaf(vv.x, e.x, s[j]);
            s[j] = fmaf(vv.y, e.y, s[j]);
            s[j] = fmaf(vv.z, e.z, s[j]);
            s[j] = fmaf(vv.w, e.w, s[j]);
        }
    }

#pragma unroll
    for (int j = 0; j < 4; ++j) {
        float t = s[j];
#pragma unroll
        for (int o = 16; o; o >>= 1)
            t += __shfl_down_sync(0xffffffffu, t, o);
        if (lane == 0) out[b * L_ + l0 + j] = t;
    }

    // ---- arrival: is this the last block for row b? ----
    __threadfence();
    __syncthreads();
    if (tid == 0) {
        const int old = atomicAdd(&g_cnt[b], 1);
        s_last = (old == gridDim.x - 1);
    }
    __syncthreads();
    if (!s_last) return;

    // ---- softmax epilogue on L2-hot row (one block per b) ----
    float4* __restrict__ o4 = (float4*)(out + b * L_);   // 1024 float4
    float4 x0 = o4[tid];
    float4 x1 = o4[tid + 512];

    float m = fmaxf(fmaxf(fmaxf(x0.x, x0.y), fmaxf(x0.z, x0.w)),
                    fmaxf(fmaxf(x1.x, x1.y), fmaxf(x1.z, x1.w)));
#pragma unroll
    for (int o = 16; o; o >>= 1) m = fmaxf(m, __shfl_xor_sync(0xffffffffu, m, o));
    if (lane == 0) red[warp] = m;
    __syncthreads();
    if (tid < 32) {
        float t = (lane < 16) ? red[lane] : -1e30f;
#pragma unroll
        for (int o = 8; o; o >>= 1) t = fmaxf(t, __shfl_xor_sync(0xffffffffu, t, o));
        red[lane & 15] = t;
    }
    __syncthreads();
    m = red[0];

    x0.x = __expf(x0.x - m); x0.y = __expf(x0.y - m);
    x0.z = __expf(x0.z - m); x0.w = __expf(x0.w - m);
    x1.x = __expf(x1.x - m); x1.y = __expf(x1.y - m);
    x1.z = __expf(x1.z - m); x1.w = __expf(x1.w - m);
    float sum = ((x0.x + x0.y) + (x0.z + x0.w)) +
                ((x1.x + x1.y) + (x1.z + x1.w));
#pragma unroll
    for (int o = 16; o; o >>= 1) sum += __shfl_xor_sync(0xffffffffu, sum, o);
    __syncthreads();
    if (lane == 0) red[warp] = sum;
    __syncthreads();
    if (tid < 32) {
        float t = (lane < 16) ? red[lane] : 0.f;
#pragma unroll
        for (int o = 8; o; o >>= 1) t += __shfl_xor_sync(0xffffffffu, t, o);
        red[lane & 15] = t;
    }
    __syncthreads();
    const float inv = 1.f / red[0];

    x0.x *= inv; x0.y *= inv; x0.z *= inv; x0.w *= inv;
    x1.x *= inv; x1.y *= inv; x1.z *= inv; x1.w *= inv;
    o4[tid]       = x0;
    o4[tid + 512] = x1;

    if (tid == 0) g_cnt[b] = 0;      // self-reset for next replay
}

// ---------------------------------------------------------------------------
extern "C" void kernel_launch(void* const* d_in, const int* in_sizes, int n_in,
                              void* d_out, int out_size) {
    const float* hid = (const float*)d_in[0];   // [1,B,H]
    const float* enc = (const float*)d_in[1];   // [L,B,H]
    const float* W   = (const float*)d_in[2];   // [H,H]
    // d_in[3] = bias: irrelevant (softmax shift invariance)
    float* out = (float*)d_out;                 // [B,1,L]

    proj_partial    <<<dim3(H_ / 128, GSPLIT, BSPLIT), 128>>>(hid, W);
    proj_reduce     <<<B_ * H_ / 128, 128>>>();
    energies_softmax<<<dim3(L_ / 64, B_), 512>>>(enc, out);
}